// round 10
// baseline (speedup 1.0000x reference)
#include <cuda_runtime.h>
#include <cstdint>

// HierarchicalSoftmax: out[b, c*320 + t] = top[b,c] + bottom[b,t]
// 2-stage PDL pipeline, pure HW sync (no atomics/spinning):
//   gemmA(rows 0-127) -> streamA(rows 0-127, PDL-sync on gemmA)
//                        || gemmB(rows 128-1023, PDL, data-disjoint, no sync)
//                        -> streamB(rows 128-1023, PDL-sync on gemmB)
// All kernels trigger programmatic-launch-completion at START (trigger only
// gates the secondary's ramp; gridsync still waits true completion).

#define BATCH      1024
#define NHID       128
#define NCLASSES   320
#define PER_CLASS  320
#define ROW_OUT    (NCLASSES * PER_CLASS)   // 102400
#define TB         256
#define QSEGS      4                        // quarter-rows per batch row
#define CLS_PER_Q  (NCLASSES / QSEGS)       // 80
#define F4_PER_Q   (CLS_PER_Q * PER_CLASS / 4)  // 6400

#define SPLIT_ROWS 128                      // rows in stage A

// GEMM tiling (frozen since R4)
#define BM 64
#define BN 16
#define ASTR 66
#define BSTR 17

__device__ float g_top[BATCH * NCLASSES];
__device__ float g_bot[BATCH * PER_CLASS];

__device__ __forceinline__ uint32_t smem_u32(const void* p) {
    uint32_t a;
    asm("{ .reg .u64 t; cvta.to.shared.u64 t, %1; cvt.u32.u64 %0, t; }" : "=r"(a) : "l"(p));
    return a;
}
__device__ __forceinline__ unsigned long long lds64(uint32_t addr) {
    unsigned long long v;
    asm volatile("ld.shared.b64 %0, [%1];" : "=l"(v) : "r"(addr));
    return v;
}
__device__ __forceinline__ unsigned long long dup2(float x) {
    unsigned long long r;
    asm("mov.b64 %0, {%1, %1};" : "=l"(r) : "f"(x));
    return r;
}
__device__ __forceinline__ void ffma2(unsigned long long& d,
                                      unsigned long long a, unsigned long long b) {
    asm("fma.rn.f32x2 %0, %1, %2, %0;" : "+l"(d) : "l"(a), "l"(b));
}
__device__ __forceinline__ void unpk(float& lo, float& hi, unsigned long long v) {
    asm("mov.b64 {%0, %1}, %2;" : "=f"(lo), "=f"(hi) : "l"(v));
}

// ---------------- packed-f32x2 tiled dual GEMM (rows [bm_off*64, ...)) ----------------
__global__ __launch_bounds__(128) void hs_gemm(
    const float* __restrict__ in,
    const float* __restrict__ Wtop,
    const float* __restrict__ btop,
    const float* __restrict__ Wbot,
    const float* __restrict__ bbot,
    int bm_off)
{
    // Fire the PDL completion event ASAP: lets the next kernel start ramping
    // while this grid executes. gridsync in the secondary still waits for this
    // grid's true completion, so this is always safe.
    cudaTriggerProgrammaticLaunchCompletion();

    __shared__ float A2[NHID * ASTR];
    __shared__ float B2[NHID * BSTR];

    const int bm  = bm_off + blockIdx.x;
    const int bn  = blockIdx.y;
    const int tid = threadIdx.x;
    const bool is_top = (bn < NCLASSES / BN);
    const int  jbase  = bn * BN;

    {
        const float* src = in + (size_t)bm * BM * NHID + tid;
        #pragma unroll 8
        for (int row = 0; row < BM; row++)
            A2[tid * ASTR + row] = src[(size_t)row * NHID];
    }

    if (is_top) {
        const int jj = tid & 15;
        const int k0 = tid >> 4;
        #pragma unroll
        for (int it = 0; it < 16; it++) {
            const int k = it * 8 + k0;
            B2[k * BSTR + jj] = Wtop[k * NCLASSES + jbase + jj];
        }
    } else {
        const int klo = tid & 31;
        const int j0  = tid >> 5;
        #pragma unroll
        for (int it = 0; it < 4; it++) {
            const int jj = it * 4 + j0;
            const float* src = Wbot + (size_t)(jbase - NCLASSES + jj) * NHID;
            #pragma unroll
            for (int kk = 0; kk < 4; kk++) {
                const int k = kk * 32 + klo;
                B2[k * BSTR + jj] = src[k];
            }
        }
    }
    __syncthreads();

    const int tr = tid >> 3;
    const int tc = tid & 7;

    unsigned long long acc00 = 0, acc01 = 0, acc10 = 0, acc11 = 0;
    const uint32_t sA = smem_u32(A2) + (tr * 4) * 4;
    const float* Bp = B2 + tc * 2;

    #pragma unroll 4
    for (int k = 0; k < NHID; k++) {
        unsigned long long a01 = lds64(sA + k * (ASTR * 4));
        unsigned long long a23 = lds64(sA + k * (ASTR * 4) + 8);
        unsigned long long b0 = dup2(Bp[k * BSTR + 0]);
        unsigned long long b1 = dup2(Bp[k * BSTR + 1]);
        ffma2(acc00, a01, b0); ffma2(acc01, a01, b1);
        ffma2(acc10, a23, b0); ffma2(acc11, a23, b1);
    }

    const int row0 = bm * BM + tr * 4;
    const int jg   = jbase + tc * 2;
    float r0c0, r1c0, r2c0, r3c0, r0c1, r1c1, r2c1, r3c1;
    unpk(r0c0, r1c0, acc00); unpk(r2c0, r3c0, acc10);
    unpk(r0c1, r1c1, acc01); unpk(r2c1, r3c1, acc11);

    float bias0, bias1;
    float* dst;
    int stride, joff;
    if (is_top) {
        bias0 = btop[jg]; bias1 = btop[jg + 1];
        dst = g_top; stride = NCLASSES; joff = jg;
    } else {
        bias0 = bbot[jg - NCLASSES]; bias1 = bbot[jg - NCLASSES + 1];
        dst = g_bot; stride = PER_CLASS; joff = jg - NCLASSES;
    }
    float2 v0 = {r0c0 + bias0, r0c1 + bias1};
    float2 v1 = {r1c0 + bias0, r1c1 + bias1};
    float2 v2 = {r2c0 + bias0, r2c1 + bias1};
    float2 v3 = {r3c0 + bias0, r3c1 + bias1};
    *reinterpret_cast<float2*>(dst + (size_t)(row0 + 0) * stride + joff) = v0;
    *reinterpret_cast<float2*>(dst + (size_t)(row0 + 1) * stride + joff) = v1;
    *reinterpret_cast<float2*>(dst + (size_t)(row0 + 2) * stride + joff) = v2;
    *reinterpret_cast<float2*>(dst + (size_t)(row0 + 3) * stride + joff) = v3;
}

// ---------------- broadcast-add stream, quarter-row CTAs (R9-proven) ----------------
__global__ __launch_bounds__(TB) void hs_stream(float* __restrict__ out, int b_off)
{
    // Let the NEXT kernel in the PDL chain start ramping immediately.
    cudaTriggerProgrammaticLaunchCompletion();

    __shared__ float  top_s[CLS_PER_Q];
    __shared__ float4 bot_s[PER_CLASS / 4];

    const int b   = b_off + (blockIdx.x >> 2);
    const int q   = blockIdx.x & 3;
    const int tid = threadIdx.x;

    // Row-invariant setup before the dependency sync (overlaps predecessor).
    int cm[5];
    #pragma unroll
    for (int m = 0; m < 5; m++) cm[m] = (tid + TB * m) / 80;   // 0..15

    float4* __restrict__ out4 =
        reinterpret_cast<float4*>(out + (size_t)b * ROW_OUT) + q * F4_PER_Q;

    // HW wait for the predecessor grid's completion + visibility.
    cudaGridDependencySynchronize();

    if (tid < 80) {
        bot_s[tid] = reinterpret_cast<const float4*>(g_bot + b * PER_CLASS)[tid];
    } else if (tid < 80 + CLS_PER_Q) {
        top_s[tid - 80] = g_top[b * NCLASSES + q * CLS_PER_Q + (tid - 80)];
    }
    __syncthreads();

    float4 bv[5];
    #pragma unroll
    for (int m = 0; m < 5; m++)
        bv[m] = bot_s[(tid + TB * m) % 80];

    #pragma unroll
    for (int p = 0; p < 5; p++) {
        #pragma unroll
        for (int m = 0; m < 5; m++) {
            const float tv = top_s[cm[m] + 16 * p];
            float4 v = bv[m];
            v.x += tv; v.y += tv; v.z += tv; v.w += tv;
            __stcs(out4 + p * (5 * TB) + m * TB + tid, v);
        }
    }
}

static inline void launch_pdl(void* fn, dim3 grid, dim3 block,
                              void** args) {
    cudaLaunchConfig_t cfg = {};
    cfg.gridDim  = grid;
    cfg.blockDim = block;
    cfg.dynamicSmemBytes = 0;
    cfg.stream = 0;
    cudaLaunchAttribute attr[1];
    attr[0].id = cudaLaunchAttributeProgrammaticStreamSerialization;
    attr[0].val.programmaticStreamSerializationAllowed = 1;
    cfg.attrs = attr;
    cfg.numAttrs = 1;
    cudaLaunchKernelExC(&cfg, fn, args);
}

extern "C" void kernel_launch(void* const* d_in, const int* in_sizes, int n_in,
                              void* d_out, int out_size) {
    const float* in   = (const float*)d_in[0];
    const float* Wtop = (const float*)d_in[1];
    const float* btop = (const float*)d_in[2];
    const float* Wbot = (const float*)d_in[3];
    const float* bbot = (const float*)d_in[4];
    float* out = (float*)d_out;

    int bm_off_a = 0;
    int bm_off_b = SPLIT_ROWS / BM;                 // 2
    int b_off_a  = 0;
    int b_off_b  = SPLIT_ROWS;                      // 128

    // Stage A GEMM: rows 0-127. Normal launch -> serializes against previous
    // graph replay (safe reuse of g_top/g_bot).
    hs_gemm<<<dim3(SPLIT_ROWS / BM, 40), 128>>>(in, Wtop, btop, Wbot, bbot, bm_off_a);

    // Stage A stream: rows 0-127 (512 CTAs). PDL: ramps during gemmA,
    // gridsync waits gemmA completion.
    {
        void* args[] = {(void*)&out, (void*)&b_off_a};
        launch_pdl((void*)hs_stream, dim3(SPLIT_ROWS * QSEGS, 1, 1), dim3(TB, 1, 1), args);
    }

    // Stage B GEMM: rows 128-1023 (560 CTAs). PDL: launches as soon as streamA
    // triggers (i.e., immediately), runs CONCURRENTLY with streamA's stores.
    // No gridsync needed: fully data-disjoint from streamA.
    {
        void* args[] = {(void*)&in, (void*)&Wtop, (void*)&btop,
                        (void*)&Wbot, (void*)&bbot, (void*)&bm_off_b};
        launch_pdl((void*)hs_gemm,
                   dim3((BATCH - SPLIT_ROWS) / BM, 40), dim3(128, 1, 1), args);
    }

    // Stage B stream: rows 128-1023 (3584 CTAs). PDL: gridsync waits gemmB,
    // which finishes under streamA's store window -> stores flow continuously.
    {
        void* args[] = {(void*)&out, (void*)&b_off_b};
        launch_pdl((void*)hs_stream,
                   dim3((BATCH - SPLIT_ROWS) * QSEGS, 1, 1), dim3(TB, 1, 1), args);
    }
}

// round 11
// speedup vs baseline: 1.0866x; 1.0866x over previous
#include <cuda_runtime.h>
#include <cstdint>

// HierarchicalSoftmax: out[b, c*320 + t] = top[b,c] + bottom[b,t]
// Phase A: f32x2-packed tiled GEMM -> g_top/g_bot, PDL trigger at START
//          (secondary ramps + parks at gridsync while GEMM executes).
// Phase B: broadcast-add stream (R9-proven: TB=256, grid=4096), PDL-launched;
//          gridsync is a HW wait for true GEMM completion.

#define BATCH      1024
#define NHID       128
#define NCLASSES   320
#define PER_CLASS  320
#define ROW_OUT    (NCLASSES * PER_CLASS)   // 102400
#define TB         256
#define QSEGS      4                        // quarter-rows per batch row
#define CLS_PER_Q  (NCLASSES / QSEGS)       // 80
#define F4_PER_Q   (CLS_PER_Q * PER_CLASS / 4)  // 6400

// GEMM tiling (frozen)
#define BM 64
#define BN 16
#define ASTR 66
#define BSTR 17

__device__ float g_top[BATCH * NCLASSES];
__device__ float g_bot[BATCH * PER_CLASS];

__device__ __forceinline__ uint32_t smem_u32(const void* p) {
    uint32_t a;
    asm("{ .reg .u64 t; cvta.to.shared.u64 t, %1; cvt.u32.u64 %0, t; }" : "=r"(a) : "l"(p));
    return a;
}
__device__ __forceinline__ unsigned long long lds64(uint32_t addr) {
    unsigned long long v;
    asm volatile("ld.shared.b64 %0, [%1];" : "=l"(v) : "r"(addr));
    return v;
}
__device__ __forceinline__ unsigned long long dup2(float x) {
    unsigned long long r;
    asm("mov.b64 %0, {%1, %1};" : "=l"(r) : "f"(x));
    return r;
}
__device__ __forceinline__ void ffma2(unsigned long long& d,
                                      unsigned long long a, unsigned long long b) {
    asm("fma.rn.f32x2 %0, %1, %2, %0;" : "+l"(d) : "l"(a), "l"(b));
}
__device__ __forceinline__ void unpk(float& lo, float& hi, unsigned long long v) {
    asm("mov.b64 {%0, %1}, %2;" : "=f"(lo), "=f"(hi) : "l"(v));
}

// ---------------- Kernel A: packed-f32x2 tiled dual GEMM ----------------
__global__ __launch_bounds__(128) void hs_gemm(
    const float* __restrict__ in,
    const float* __restrict__ Wtop,
    const float* __restrict__ btop,
    const float* __restrict__ Wbot,
    const float* __restrict__ bbot)
{
    // Trigger at START: the stream grid ramps & parks at its gridsync while
    // this grid executes. gridsync still waits for this grid's completion.
    cudaTriggerProgrammaticLaunchCompletion();

    __shared__ float A2[NHID * ASTR];
    __shared__ float B2[NHID * BSTR];

    const int bm  = blockIdx.x;
    const int bn  = blockIdx.y;
    const int tid = threadIdx.x;
    const bool is_top = (bn < NCLASSES / BN);
    const int  jbase  = bn * BN;

    {
        const float* src = in + (size_t)bm * BM * NHID + tid;
        #pragma unroll 8
        for (int row = 0; row < BM; row++)
            A2[tid * ASTR + row] = src[(size_t)row * NHID];
    }

    if (is_top) {
        const int jj = tid & 15;
        const int k0 = tid >> 4;
        #pragma unroll
        for (int it = 0; it < 16; it++) {
            const int k = it * 8 + k0;
            B2[k * BSTR + jj] = Wtop[k * NCLASSES + jbase + jj];
        }
    } else {
        const int klo = tid & 31;
        const int j0  = tid >> 5;
        #pragma unroll
        for (int it = 0; it < 4; it++) {
            const int jj = it * 4 + j0;
            const float* src = Wbot + (size_t)(jbase - NCLASSES + jj) * NHID;
            #pragma unroll
            for (int kk = 0; kk < 4; kk++) {
                const int k = kk * 32 + klo;
                B2[k * BSTR + jj] = src[k];
            }
        }
    }
    __syncthreads();

    const int tr = tid >> 3;
    const int tc = tid & 7;

    unsigned long long acc00 = 0, acc01 = 0, acc10 = 0, acc11 = 0;
    const uint32_t sA = smem_u32(A2) + (tr * 4) * 4;
    const float* Bp = B2 + tc * 2;

    #pragma unroll 4
    for (int k = 0; k < NHID; k++) {
        unsigned long long a01 = lds64(sA + k * (ASTR * 4));
        unsigned long long a23 = lds64(sA + k * (ASTR * 4) + 8);
        unsigned long long b0 = dup2(Bp[k * BSTR + 0]);
        unsigned long long b1 = dup2(Bp[k * BSTR + 1]);
        ffma2(acc00, a01, b0); ffma2(acc01, a01, b1);
        ffma2(acc10, a23, b0); ffma2(acc11, a23, b1);
    }

    const int row0 = bm * BM + tr * 4;
    const int jg   = jbase + tc * 2;
    float r0c0, r1c0, r2c0, r3c0, r0c1, r1c1, r2c1, r3c1;
    unpk(r0c0, r1c0, acc00); unpk(r2c0, r3c0, acc10);
    unpk(r0c1, r1c1, acc01); unpk(r2c1, r3c1, acc11);

    float bias0, bias1;
    float* dst;
    int stride, joff;
    if (is_top) {
        bias0 = btop[jg]; bias1 = btop[jg + 1];
        dst = g_top; stride = NCLASSES; joff = jg;
    } else {
        bias0 = bbot[jg - NCLASSES]; bias1 = bbot[jg - NCLASSES + 1];
        dst = g_bot; stride = PER_CLASS; joff = jg - NCLASSES;
    }
    float2 v0 = {r0c0 + bias0, r0c1 + bias1};
    float2 v1 = {r1c0 + bias0, r1c1 + bias1};
    float2 v2 = {r2c0 + bias0, r2c1 + bias1};
    float2 v3 = {r3c0 + bias0, r3c1 + bias1};
    *reinterpret_cast<float2*>(dst + (size_t)(row0 + 0) * stride + joff) = v0;
    *reinterpret_cast<float2*>(dst + (size_t)(row0 + 1) * stride + joff) = v1;
    *reinterpret_cast<float2*>(dst + (size_t)(row0 + 2) * stride + joff) = v2;
    *reinterpret_cast<float2*>(dst + (size_t)(row0 + 3) * stride + joff) = v3;
}

// ---------------- Kernel B: broadcast-add stream, quarter-row CTAs ----------------
__global__ __launch_bounds__(TB) void hs_stream(float* __restrict__ out)
{
    __shared__ float  top_s[CLS_PER_Q];
    __shared__ float4 bot_s[PER_CLASS / 4];

    const int b   = blockIdx.x >> 2;
    const int q   = blockIdx.x & 3;
    const int tid = threadIdx.x;

    // Row-invariant setup before the dependency sync (overlaps GEMM exec).
    int cm[5];
    #pragma unroll
    for (int m = 0; m < 5; m++) cm[m] = (tid + TB * m) / 80;   // 0..15

    float4* __restrict__ out4 =
        reinterpret_cast<float4*>(out + (size_t)b * ROW_OUT) + q * F4_PER_Q;

    // HW wait: parks here (no issue slots) until the GEMM grid completes.
    cudaGridDependencySynchronize();

    if (tid < 80) {
        bot_s[tid] = reinterpret_cast<const float4*>(g_bot + b * PER_CLASS)[tid];
    } else if (tid < 80 + CLS_PER_Q) {
        top_s[tid - 80] = g_top[b * NCLASSES + q * CLS_PER_Q + (tid - 80)];
    }
    __syncthreads();

    float4 bv[5];
    #pragma unroll
    for (int m = 0; m < 5; m++)
        bv[m] = bot_s[(tid + TB * m) % 80];

    #pragma unroll
    for (int p = 0; p < 5; p++) {
        #pragma unroll
        for (int m = 0; m < 5; m++) {
            const float tv = top_s[cm[m] + 16 * p];
            float4 v = bv[m];
            v.x += tv; v.y += tv; v.z += tv; v.w += tv;
            __stcs(out4 + p * (5 * TB) + m * TB + tid, v);
        }
    }
}

extern "C" void kernel_launch(void* const* d_in, const int* in_sizes, int n_in,
                              void* d_out, int out_size) {
    const float* in   = (const float*)d_in[0];
    const float* Wtop = (const float*)d_in[1];
    const float* btop = (const float*)d_in[2];
    const float* Wbot = (const float*)d_in[3];
    const float* bbot = (const float*)d_in[4];
    float* out = (float*)d_out;

    // GEMM: normal launch (serializes against previous graph replay).
    dim3 grid(BATCH / BM, (NCLASSES + PER_CLASS) / BN);   // 16 x 40
    hs_gemm<<<grid, 128>>>(in, Wtop, btop, Wbot, bbot);

    // Stream: PDL launch; ramps during GEMM (trigger fires at GEMM start),
    // parks at gridsync, stores begin the instant the GEMM grid retires.
    cudaLaunchConfig_t cfg = {};
    cfg.gridDim  = dim3(BATCH * QSEGS, 1, 1);             // 4096
    cfg.blockDim = dim3(TB, 1, 1);
    cfg.dynamicSmemBytes = 0;
    cfg.stream = 0;
    cudaLaunchAttribute attr[1];
    attr[0].id = cudaLaunchAttributeProgrammaticStreamSerialization;
    attr[0].val.programmaticStreamSerializationAllowed = 1;
    cfg.attrs = attr;
    cfg.numAttrs = 1;
    cudaLaunchKernelEx(&cfg, hs_stream, out);
}